// round 11
// baseline (speedup 1.0000x reference)
#include <cuda_runtime.h>
#include <cuda_bf16.h>
#include <cstdint>

#define THREADS 256
#define NCOLS   8192
#define FVECS   8            // float4 chunks per thread: 8*4*256 = 8192
#define KTOP    64
#define CAP     512          // candidate buffer (expected ~186, 24 sigma)
#define MCAP    512          // marked-vec4 buffer (expected ~170)
#define TBCAP   128          // in-bin buffer for final exact rank
#define PIVOT   2.0f
#define CTAS_PER_SM 3
#define GRID    (148 * CTAS_PER_SM)
#define ROWBYTES (NCOLS * 4)   // 32 KB
#define DSMEM   (2 * ROWBYTES) // two row buffers

// Monotone ticket counter; each CTA consumes tickets until (and including)
// its FIRST stop ticket, then never takes another. Every launch therefore
// consumes exactly rows + GRID tickets, so row = ticket % (rows + GRID) is
// launch-invariant (graph-replay safe, no reset kernel).
__device__ unsigned long long g_ticket;

__device__ __forceinline__ unsigned mono(unsigned u) {
    return u ^ ((unsigned)((int)u >> 31) | 0x80000000u);
}

__device__ __forceinline__ unsigned smem_u32(const void* p) {
    unsigned a;
    asm("{ .reg .u64 t; cvta.to.shared.u64 t, %1; cvt.u32.u64 %0, t; }"
        : "=r"(a) : "l"(p));
    return a;
}

__device__ __forceinline__ void mbar_init(unsigned mbar, unsigned cnt) {
    asm volatile("mbarrier.init.shared.b64 [%0], %1;" :: "r"(mbar), "r"(cnt)
                 : "memory");
}
__device__ __forceinline__ void mbar_expect_tx(unsigned mbar, unsigned bytes) {
    asm volatile("mbarrier.arrive.expect_tx.shared.b64 _, [%0], %1;"
                 :: "r"(mbar), "r"(bytes) : "memory");
}
__device__ __forceinline__ void mbar_wait(unsigned mbar, unsigned parity) {
    asm volatile(
        "{\n\t.reg .pred P;\n\t"
        "W_%=:\n\t"
        "mbarrier.try_wait.parity.acquire.cta.shared::cta.b64 P, [%0], %1, 0x989680;\n\t"
        "@P bra D_%=;\n\t"
        "bra W_%=;\n\t"
        "D_%=:\n\t}"
        :: "r"(mbar), "r"(parity) : "memory");
}
__device__ __forceinline__ void bulk_g2s(unsigned dst, const void* src,
                                         unsigned bytes, unsigned mbar) {
    asm volatile(
        "cp.async.bulk.shared::cluster.global.mbarrier::complete_tx::bytes "
        "[%0], [%1], %2, [%3];"
        :: "r"(dst), "l"(src), "r"(bytes), "r"(mbar) : "memory");
}

__global__ __launch_bounds__(THREADS, CTAS_PER_SM)
void topk_mask_kernel(const float* __restrict__ x, float* __restrict__ out,
                      int rows) {
    extern __shared__ __align__(128) unsigned char dynbuf[];  // 2 row buffers
    const int tid  = threadIdx.x;
    const int lane = tid & 31;
    const int wid  = tid >> 5;
    const unsigned long long EPOCH = (unsigned long long)rows + GRID;

    __shared__ unsigned hist[256];
    __shared__ unsigned wsum[8];
    __shared__ unsigned long long sh_t;
    __shared__ unsigned sh_cnt, sh_mcnt, sh_B, sh_kB, sh_tc;
    __shared__ unsigned long long sh_T;
    __shared__ unsigned long long cand[CAP];
    __shared__ unsigned long long mbuf[MCAP / 2];   // marks(u32)/tb(u64) reuse
    __shared__ __align__(8) unsigned long long mbar_s[2];
    unsigned* marks = reinterpret_cast<unsigned*>(mbuf);

    const unsigned mb0 = smem_u32(&mbar_s[0]);
    const unsigned mb1 = smem_u32(&mbar_s[1]);
    const unsigned buf0 = smem_u32(dynbuf);
    const unsigned buf1 = buf0 + ROWBYTES;

    // ---- Prologue: init barriers, take first ticket, start first fetch ----
    if (tid == 0) {
        sh_cnt = 0u; sh_mcnt = 0u; sh_tc = 0u;
        mbar_init(mb0, 1);
        mbar_init(mb1, 1);
        sh_t = atomicAdd(&g_ticket, 1ull);
    }
    __syncthreads();
    unsigned r_cur = (unsigned)(sh_t % EPOCH);
    if (r_cur >= (unsigned)rows) return;          // consumed our stop ticket

    if (tid == 0) {
        mbar_expect_tx(mb0, ROWBYTES);
        bulk_g2s(buf0, x + (size_t)r_cur * NCOLS, ROWBYTES, mb0);
        sh_t = atomicAdd(&g_ticket, 1ull);        // take T1 (allowed: T0 valid)
    }
    __syncthreads();
    unsigned r_next = (unsigned)(sh_t % EPOCH);
    bool v_next = r_next < (unsigned)rows;
    if (tid == 0 && v_next) {
        mbar_expect_tx(mb1, ROWBYTES);
        bulk_g2s(buf1, x + (size_t)r_next * NCOLS, ROWBYTES, mb1);
    }

    int cur = 0;
    unsigned phase[2] = {0u, 0u};

    for (;;) {
        const unsigned mb  = cur ? mb1 : mb0;
        const unsigned bfa = cur ? buf1 : buf0;
        mbar_wait(mb, phase[cur]);
        phase[cur] ^= 1u;

        const float4* __restrict__ b4 = reinterpret_cast<const float4*>(
            dynbuf + (size_t)cur * ROWBYTES);
        float4* __restrict__ out4 =
            reinterpret_cast<float4*>(out + (size_t)r_cur * NCOLS);
        float* __restrict__ orow = out + (size_t)r_cur * NCOLS;

        // ---- Phase 1: row from SMEM; stream zeros out; mark vec4s ----
        const float4 z = make_float4(0.f, 0.f, 0.f, 0.f);
        #pragma unroll
        for (int jj = 0; jj < FVECS; ++jj) {
            const int idx = tid + THREADS * jj;
            const float4 v = b4[idx];
            out4[idx] = z;
            const float m = fmaxf(fmaxf(v.x, v.y), fmaxf(v.z, v.w));
            if (m > PIVOT) {
                const unsigned pos = atomicAdd(&sh_mcnt, 1u);
                if (pos < MCAP) marks[pos] = (unsigned)idx;
            }
        }
        __syncthreads();
        const unsigned mcnt = sh_mcnt;
        if (tid == 0 && v_next) sh_t = atomicAdd(&g_ticket, 1ull); // take T_{k+2}
        if (tid < 128) hist[tid] = 0u;

        // ---- Phase 2: rescan marked vec4s from SMEM, exact candidates ----
        if (mcnt <= MCAP) {
            for (unsigned s = tid; s < mcnt; s += THREADS) {
                const unsigned idx = marks[s];
                const float4 v = b4[idx];
                #pragma unroll
                for (int c = 0; c < 4; ++c) {
                    const float f = (&v.x)[c];
                    if (f > PIVOT) {
                        const unsigned pos = atomicAdd(&sh_cnt, 1u);
                        if (pos < CAP)
                            cand[pos] =
                                ((unsigned long long)__float_as_uint(f) << 13) |
                                (unsigned long long)(8191u - (4u * idx + (unsigned)c));
                    }
                }
            }
        }
        __syncthreads();     // all smem-buffer reads done; sh_t visible
        const unsigned cnt = sh_cnt;

        // ---- Refill this buffer with row T_{k+2} (engine-driven fetch) ----
        unsigned r_new = 0xffffffffu;
        if (v_next) r_new = (unsigned)(sh_t % EPOCH);
        if (tid == 0 && r_new < (unsigned)rows) {
            mbar_expect_tx(mb, ROWBYTES);
            bulk_g2s(bfa, x + (size_t)r_new * NCOLS, ROWBYTES, mb);
        }

        bool done = false;
        if (mcnt <= MCAP && cnt >= KTOP && cnt <= CAP) {
            // ---- Phase 3: 128-bin monotone histogram over candidate bits ----
            for (unsigned s = tid; s < cnt; s += THREADS) {
                const unsigned bits = (unsigned)(cand[s] >> 13);
                unsigned d = (bits - 0x40000000u) >> 17;
                if (d > 127u) d = 127u;
                atomicAdd(&hist[d], 1u);
            }
            __syncthreads();

            unsigned v = 0u, sc = 0u;
            if (tid < 128) {
                v = hist[127 - tid];
                sc = v;
                #pragma unroll
                for (int off = 1; off < 32; off <<= 1) {
                    const unsigned y = __shfl_up_sync(0xffffffffu, sc, off);
                    if (lane >= off) sc += y;
                }
                if (lane == 31) wsum[wid] = sc;
            }
            __syncthreads();
            if (tid < 128) {
                unsigned add = 0u;
                #pragma unroll
                for (int w = 0; w < 4; ++w) add += (w < wid) ? wsum[w] : 0u;
                const unsigned incl = sc + add;
                const unsigned excl = incl - v;
                if (excl < KTOP && KTOP <= incl) {
                    sh_B  = 127u - (unsigned)tid;
                    sh_kB = KTOP - excl;
                }
            }
            __syncthreads();
            const unsigned B  = sh_B;
            const unsigned kB = sh_kB;

            // ---- Phase 4: collect in-bin candidates (expected 2-5) ----
            unsigned long long* tb = mbuf;
            for (unsigned s = tid; s < cnt; s += THREADS) {
                const unsigned long long cv = cand[s];
                const unsigned bits = (unsigned)(cv >> 13);
                unsigned d = (bits - 0x40000000u) >> 17;
                if (d > 127u) d = 127u;
                if (d == B) {
                    const unsigned p2 = atomicAdd(&sh_tc, 1u);
                    if (p2 < TBCAP) tb[p2] = cv;
                }
            }
            __syncthreads();
            const unsigned tc = sh_tc;

            if (tc <= TBCAP) {
                for (unsigned s = tid; s < tc; s += THREADS) {
                    const unsigned long long vv = tb[s];
                    unsigned rr = 0u;
                    for (unsigned j = 0; j < tc; ++j)
                        rr += (tb[j] > vv) ? 1u : 0u;
                    if (rr == kB - 1u) sh_T = vv;
                }
                __syncthreads();
                const unsigned long long T = sh_T;
                if (tid == 0) { sh_cnt = 0u; sh_mcnt = 0u; sh_tc = 0u; }

                // ---- Phase 5: scatter the 64 kept values over the zeros ----
                for (unsigned s = tid; s < cnt; s += THREADS) {
                    const unsigned long long cv = cand[s];
                    const unsigned bits = (unsigned)(cv >> 13);
                    unsigned d = (bits - 0x40000000u) >> 17;
                    if (d > 127u) d = 127u;
                    if (d > B || (d == B && cv >= T)) {
                        const unsigned col = 8191u - (unsigned)(cv & 8191ull);
                        orow[col] = __uint_as_float(bits);
                    }
                }
                done = true;
            }
        }

        if (!done) {
            // ============ Generic fallback (never taken for N(0,1)) ==========
            // Reads the row from GLOBAL memory (smem buffer may be refilling).
            const float4* __restrict__ in4 =
                reinterpret_cast<const float4*>(x + (size_t)r_cur * NCOLS);
            __shared__ unsigned sh_prefix, sh_kk, sh_tcnt, sh_cut;
            __syncthreads();
            if (tid == 0) { sh_prefix = 0u; sh_kk = KTOP; }

            for (int p = 0; p < 4; ++p) {
                __syncthreads();
                const unsigned prefix = sh_prefix;
                const unsigned kRem   = sh_kk;
                hist[tid] = 0u;
                __syncthreads();
                for (int jj = 0; jj < FVECS; ++jj) {
                    const float4 v = in4[tid + THREADS * jj];
                    #pragma unroll
                    for (int c = 0; c < 4; ++c) {
                        const unsigned key = mono(__float_as_uint((&v.x)[c]));
                        const bool act = (p == 0) ||
                                         ((key >> (32 - 8 * p)) == prefix);
                        if (act)
                            atomicAdd(&hist[(key >> (24 - 8 * p)) & 0xffu], 1u);
                    }
                }
                __syncthreads();
                const unsigned v  = hist[255 - tid];
                unsigned sc = v;
                #pragma unroll
                for (int off = 1; off < 32; off <<= 1) {
                    const unsigned y = __shfl_up_sync(0xffffffffu, sc, off);
                    if (lane >= off) sc += y;
                }
                if (lane == 31) wsum[wid] = sc;
                __syncthreads();
                unsigned add = 0u;
                #pragma unroll
                for (int w = 0; w < 8; ++w) add += (w < wid) ? wsum[w] : 0u;
                const unsigned incl = sc + add;
                const unsigned excl = incl - v;
                if (excl < kRem && kRem <= incl) {
                    sh_prefix = (prefix << 8) | (255u - (unsigned)tid);
                    sh_kk     = kRem - excl;
                }
            }
            __syncthreads();
            const unsigned Tk = sh_prefix;
            const unsigned kT = sh_kk;

            unsigned* tcol = (unsigned*)cand;
            if (tid == 0) sh_tcnt = 0u;
            __syncthreads();
            for (int jj = 0; jj < FVECS; ++jj) {
                const float4 v = in4[tid + THREADS * jj];
                #pragma unroll
                for (int c = 0; c < 4; ++c) {
                    const unsigned key = mono(__float_as_uint((&v.x)[c]));
                    if (key == Tk) {
                        const unsigned col =
                            4u * ((unsigned)tid + THREADS * jj) + (unsigned)c;
                        const unsigned pos = atomicAdd(&sh_tcnt, 1u);
                        if (pos < 2u * CAP) tcol[pos] = col;
                    }
                }
            }
            __syncthreads();
            if (tid == 0) {
                unsigned c = sh_tcnt; if (c > 2u * CAP) c = 2u * CAP;
                unsigned cut = 0xffffffffu;
                for (unsigned s = 0; s < kT; ++s) {
                    unsigned mn = 0xffffffffu, mi = 0u;
                    for (unsigned i = 0; i < c; ++i)
                        if (tcol[i] < mn) { mn = tcol[i]; mi = i; }
                    tcol[mi] = 0xffffffffu;
                    cut = mn;
                }
                sh_cut = cut;
            }
            __syncthreads();
            const unsigned cut = sh_cut;

            for (int jj = 0; jj < FVECS; ++jj) {
                const float4 v = in4[tid + THREADS * jj];
                float4 o;
                #pragma unroll
                for (int c = 0; c < 4; ++c) {
                    const unsigned key = mono(__float_as_uint((&v.x)[c]));
                    const unsigned col =
                        4u * ((unsigned)tid + THREADS * jj) + (unsigned)c;
                    const bool keep = (key > Tk) || (key == Tk && col <= cut);
                    (&o.x)[c] = keep ? (&v.x)[c] : 0.0f;
                }
                out4[tid + THREADS * jj] = o;
            }
            __syncthreads();
            if (tid == 0) { sh_cnt = 0u; sh_mcnt = 0u; sh_tc = 0u; }
        }

        __syncthreads();   // counter resets visible before next row's pushes

        // ---- Rotate pipeline ----
        if (!v_next) break;          // the row just processed was the last valid
        r_cur  = r_next;
        r_next = r_new;
        v_next = r_new < (unsigned)rows;
        cur ^= 1;
    }
}

extern "C" void kernel_launch(void* const* d_in, const int* in_sizes, int n_in,
                              void* d_out, int out_size) {
    const float* x = (const float*)d_in[0];
    float* out = (float*)d_out;
    const int rows = in_sizes[0] / NCOLS;
    static bool attr_set = false;
    if (!attr_set) {
        cudaFuncSetAttribute(topk_mask_kernel,
                             cudaFuncAttributeMaxDynamicSharedMemorySize, DSMEM);
        attr_set = true;
    }
    topk_mask_kernel<<<GRID, THREADS, DSMEM>>>(x, out, rows);
}